// round 10
// baseline (speedup 1.0000x reference)
#include <cuda_runtime.h>

// Problem constants
#define TOKENS   65536          // 16*64*64
#define DDIM     256
#define KCODES   1024
#define Z_ELEMS  (TOKENS * DDIM)   // 16777216
#define BETA     0.25f
#define EPS_F    1e-5f

// Argmin tiling: CTA = 256 threads (8 warps). Warp w owns tokens w*8..w*8+7.
// Lane = code lane: thread covers k = kc + lane + j*32, j = 0..3 (KC=128).
#define TT       64                      // tokens per CTA
#define KC       128                     // codes per chunk
#define DC       32                      // d per smem stage
#define NCHUNK   (KCODES / KC)           // 8
#define DSTAGES  (DDIM / DC)             // 8
#define NSTAGES  (NCHUNK * DSTAGES)      // 64
#define NBLK_A   (TOKENS / TT)           // 1024

// smem floats: zs 16384 | se2 1024 | sz2 64 | es 2 stages x 1024 ul2 (32KB)
#define SM_SE2_F  (TT * DDIM)                        // 16384
#define SM_SZ2_F  (TT * DDIM + KCODES)               // 17408
#define SM_ES_B   ((TT * DDIM + KCODES + TT) * 4)    // 69888 bytes (16B aligned)
#define SMEM_BYTES (SM_ES_B + 2 * (DC / 4) * KC * 16)   // 102656

// Output layout (flattened reference tuple, float32):
//   [0 .. Z_ELEMS) z_q_st | [Z+0..3] commit, codebook, cluster, perplexity
//   [Z+4 .. Z+4+TOKENS) indices as float

// Scratch (device globals: no allocations allowed)
__device__ int        g_counts[KCODES];
__device__ double     g_partial[NBLK_A];
__device__ float      g_e2[KCODES];
__device__ float      g_z2[TOKENS];
// codebook repacked: [d/4][k], entry = {pack(e[4q],e[4q+1]), pack(e[4q+2],e[4q+3])}
__device__ ulonglong2 g_ctp4[(DDIM / 4) * KCODES];

// ---------------------------------------------------------------------------
// prep codebook (coalesced) + fold in histogram zeroing.
// ---------------------------------------------------------------------------
__global__ void __launch_bounds__(256) vq_prep_cb_kernel(const float* __restrict__ cb) {
    __shared__ float ct[32 * 260];
    const int tid = threadIdx.x;
    const int k0  = blockIdx.x * 32;
    if (blockIdx.x < 4) g_counts[blockIdx.x * 256 + tid] = 0;
    const float* cbb = cb + (size_t)k0 * DDIM;
    #pragma unroll
    for (int p = 0; p < 32; p++) {
        int e = tid + p * 256;            // 0..8191
        ct[(e >> 8) * 260 + (e & 255)] = cbb[e];
    }
    __syncthreads();
    if (tid < 32) {
        const float* row = &ct[tid * 260];
        float s = 0.0f;
        #pragma unroll 8
        for (int d = 0; d < DDIM; d++)
            s = __fadd_rn(s, __fmul_rn(row[d], row[d]));
        g_e2[k0 + tid] = s;
    }
    __syncthreads();
    #pragma unroll
    for (int p = 0; p < 8; p++) {
        int idx = tid + p * 256;          // 0..2047
        int dq  = idx >> 5;               // 0..63
        int kk  = idx & 31;
        const float* row = &ct[kk * 260 + dq * 4];
        float2 p01 = make_float2(row[0], row[1]);
        float2 p23 = make_float2(row[2], row[3]);
        ulonglong2 v;
        v.x = *reinterpret_cast<unsigned long long*>(&p01);
        v.y = *reinterpret_cast<unsigned long long*>(&p23);
        g_ctp4[(size_t)dq * KCODES + k0 + kk] = v;
    }
}

// ---------------------------------------------------------------------------
// prep z2: coalesced loads via padded smem transpose, reference sum order.
// ---------------------------------------------------------------------------
__global__ void __launch_bounds__(256) vq_prep_z2_kernel(const float* __restrict__ z) {
    __shared__ float zt[32 * 257];
    const int tid  = threadIdx.x;
    const int tok0 = blockIdx.x * 32;
    const float* zb = z + (size_t)tok0 * DDIM;
    #pragma unroll
    for (int p = 0; p < 32; p++) {
        int e = tid + p * 256;
        zt[(e >> 8) * 257 + (e & 255)] = zb[e];
    }
    __syncthreads();
    if (tid < 32) {
        const float* row = &zt[tid * 257];
        float s = 0.0f;
        #pragma unroll 8
        for (int d = 0; d < DDIM; d++)
            s = __fadd_rn(s, __fmul_rn(row[d], row[d]));
        g_z2[tok0 + tid] = s;
    }
}

// ---------------------------------------------------------------------------
// fused argmin + gather + loss.  Inner loop emitted as runs of 4 FMA2 that
// SHARE the eb multiplier operand slot (x-pass then y-pass per 4-token
// block) so ptxas can apply .reuse and cut the 3-bank RF conflict of the
// 3-pair f32x2 FMA to an average ~2.25 cycles/issue.
// ---------------------------------------------------------------------------
__global__ void __launch_bounds__(256, 2)
vq_argmin(const float* __restrict__ z, const float* __restrict__ cb,
          float* __restrict__ out) {
    extern __shared__ float smem[];
    float*      zs  = smem;
    float*      se2 = smem + SM_SE2_F;
    float*      sz2 = smem + SM_SZ2_F;
    ulonglong2* es  = reinterpret_cast<ulonglong2*>(
        reinterpret_cast<char*>(smem) + SM_ES_B);

    const int tid  = threadIdx.x;
    const int lane = tid & 31;
    const int w    = tid >> 5;          // warp 0..7: owns tokens w*8..w*8+7
    const int tok0 = blockIdx.x * TT;

    // Load z tile: 4096 float4s, 16 per thread, coalesced.
    {
        const float4* zg  = reinterpret_cast<const float4*>(z);
        float4*       zs4 = reinterpret_cast<float4*>(zs);
        #pragma unroll
        for (int p = 0; p < 16; p++) {
            int idx = tid + p * 256;
            zs4[idx] = zg[(size_t)tok0 * (DDIM / 4) + idx];
        }
    }
    // Stage e2 and z2 into smem.
    #pragma unroll
    for (int p = 0; p < 4; p++) {
        int idx = tid + p * 256;
        se2[idx] = g_e2[idx];
    }
    if (tid < TT) sz2[tid] = g_z2[tok0 + tid];

    float best[8];
    int   bidx[8];
    #pragma unroll
    for (int i = 0; i < 8; i++) { best[i] = 3.4e38f; bidx[i] = 0; }

    // stage prefetch: 4 x 16B cp.async per thread (16KB stage = 1024 ul2)
    #define STAGE_LOAD(S, BUF)                                                   \
    do {                                                                         \
        int kc_ = ((S) >> 3) * KC;                                               \
        int dc_ = ((S) & 7) * DC;                                                \
        _Pragma("unroll")                                                        \
        for (int q = 0; q < 4; q++) {                                            \
            int idx_ = tid + q * 256;          /* 0..1023 */                     \
            int dg_  = idx_ >> 7;              /* 0..7   */                      \
            int c_   = idx_ & 127;             /* 0..127 */                      \
            const ulonglong2* src_ =                                             \
                &g_ctp4[(size_t)((dc_ >> 2) + dg_) * KCODES + kc_ + c_];         \
            unsigned dst_ = (unsigned)__cvta_generic_to_shared(                  \
                &es[(BUF) * 1024 + idx_]);                                       \
            asm volatile("cp.async.cg.shared.global [%0], [%1], 16;\n"           \
                         :: "r"(dst_), "l"(src_));                               \
        }                                                                        \
        asm volatile("cp.async.commit_group;\n" ::: "memory");                   \
    } while (0)

    // One 4-token FMA block: x-halves first (runs of 4 sharing eb[j].x in the
    // multiplier slot), then y-halves. Per-acc order (x then y) is unchanged.
    #define FMABLOCK(B, ZB)                                                      \
    do {                                                                         \
        _Pragma("unroll")                                                        \
        for (int j = 0; j < 4; j++) {                                            \
            _Pragma("unroll")                                                    \
            for (int i = 0; i < 4; i++)                                          \
                asm volatile("fma.rn.f32x2 %0, %1, %2, %0;"                      \
                             : "+l"(acc[(B) + i][j])                             \
                             : "l"((ZB)[i].x), "l"(eb[j].x));                    \
        }                                                                        \
        _Pragma("unroll")                                                        \
        for (int j = 0; j < 4; j++) {                                            \
            _Pragma("unroll")                                                    \
            for (int i = 0; i < 4; i++)                                          \
                asm volatile("fma.rn.f32x2 %0, %1, %2, %0;"                      \
                             : "+l"(acc[(B) + i][j])                             \
                             : "l"((ZB)[i].y), "l"(eb[j].y));                    \
        }                                                                        \
    } while (0)

    STAGE_LOAD(0, 0);

    unsigned long long acc[8][4];
    int buf = 0;

    for (int s = 0; s < NSTAGES; s++) {
        if ((s & 7) == 0) {
            #pragma unroll
            for (int i = 0; i < 8; i++)
                #pragma unroll
                for (int j = 0; j < 4; j++) acc[i][j] = 0ull;
        }

        asm volatile("cp.async.wait_group 0;\n" ::: "memory");
        __syncthreads();
        if (s + 1 < NSTAGES) STAGE_LOAD(s + 1, buf ^ 1);

        const int dc = (s & 7) * DC;
        const ulonglong2* ebp = &es[buf * 1024] + lane;   // +lane base
        const float*      zap = zs + (w * 8) * DDIM + dc; // token 0, dg 0

        ulonglong2 eb[4], zcur[4], znxt[4];
        // preload za block 0 of dg 0 (tokens 0..3)
        #pragma unroll
        for (int i = 0; i < 4; i++)
            zcur[i] = *reinterpret_cast<const ulonglong2*>(zap + i * DDIM);

        #pragma unroll
        for (int dg = 0; dg < 8; dg++) {
            // eb for this dg
            #pragma unroll
            for (int j = 0; j < 4; j++) eb[j] = ebp[dg * KC + j * 32];
            // block 0 (tokens 0-3): prefetch block 1 za under the FMAs
            #pragma unroll
            for (int i = 0; i < 4; i++)
                znxt[i] = *reinterpret_cast<const ulonglong2*>(
                    zap + (4 + i) * DDIM + 4 * dg);
            FMABLOCK(0, zcur);
            // block 1 (tokens 4-7): prefetch next dg's block 0 za
            if (dg < 7) {
                #pragma unroll
                for (int i = 0; i < 4; i++)
                    zcur[i] = *reinterpret_cast<const ulonglong2*>(
                        zap + i * DDIM + 4 * (dg + 1));
            }
            FMABLOCK(4, znxt);
        }
        buf ^= 1;

        if ((s & 7) == 7) {
            int kc = (s >> 3) * KC;
            #pragma unroll
            for (int i = 0; i < 8; i++) {
                float z2v = sz2[w * 8 + i];
                #pragma unroll
                for (int j = 0; j < 4; j++) {
                    int k = kc + lane + j * 32;
                    float e2k = se2[k];
                    float lo = __uint_as_float((unsigned)(acc[i][j] & 0xFFFFFFFFull));
                    float hi = __uint_as_float((unsigned)(acc[i][j] >> 32));
                    float ze = __fadd_rn(lo, hi);
                    float dist = __fsub_rn(__fadd_rn(z2v, e2k),
                                           __fmul_rn(2.0f, ze));
                    if (dist < best[i]) { best[i] = dist; bidx[i] = k; }
                }
            }
        }
    }
    #undef STAGE_LOAD
    #undef FMABLOCK

    // --- full-warp argmin reduce per token (min dist, min index on ties) ---
    __syncthreads();                       // es region free for reuse
    int*    sfin = reinterpret_cast<int*>(
        reinterpret_cast<char*>(smem) + SM_ES_B);           // 64 ints
    double* dred = reinterpret_cast<double*>(
        reinterpret_cast<char*>(smem) + SM_ES_B + 256);     // 256 doubles

    #pragma unroll
    for (int i = 0; i < 8; i++) {
        float bd = best[i];
        int   bi = bidx[i];
        #pragma unroll
        for (int off = 16; off > 0; off >>= 1) {
            float od = __shfl_down_sync(0xFFFFFFFFu, bd, off);
            int   oi = __shfl_down_sync(0xFFFFFFFFu, bi, off);
            if (od < bd || (od == bd && oi < bi)) { bd = od; bi = oi; }
        }
        if (lane == 0) {
            int t  = w * 8 + i;
            int gt = tok0 + t;
            out[Z_ELEMS + 4 + gt] = (float)bi;
            atomicAdd(&g_counts[bi], 1);
            sfin[t] = bi;
        }
    }
    __syncthreads();

    // --- fused gather + z_q_st write + loss partial (z tile still in smem) ---
    double sacc = 0.0;
    const float4* cb4 = reinterpret_cast<const float4*>(cb);
    const float4* zs4 = reinterpret_cast<const float4*>(zs);
    float4*       o4  = reinterpret_cast<float4*>(out);
    #pragma unroll
    for (int p = 0; p < 16; p++) {
        int e4 = tid + p * 256;           // 0..4095
        int t  = e4 >> 6;
        int d4 = e4 & 63;
        int idx = sfin[t];
        float4 zq = cb4[(size_t)idx * (DDIM / 4) + d4];
        float4 zz = zs4[e4];
        float4 o;
        o.x = __fadd_rn(zz.x, __fsub_rn(zq.x, zz.x));
        o.y = __fadd_rn(zz.y, __fsub_rn(zq.y, zz.y));
        o.z = __fadd_rn(zz.z, __fsub_rn(zq.z, zz.z));
        o.w = __fadd_rn(zz.w, __fsub_rn(zq.w, zz.w));
        o4[(size_t)tok0 * (DDIM / 4) + e4] = o;
        float dx = __fsub_rn(zz.x, zq.x);
        float dy = __fsub_rn(zz.y, zq.y);
        float dz = __fsub_rn(zz.z, zq.z);
        float dw = __fsub_rn(zz.w, zq.w);
        sacc += (double)__fmul_rn(dx, dx);
        sacc += (double)__fmul_rn(dy, dy);
        sacc += (double)__fmul_rn(dz, dz);
        sacc += (double)__fmul_rn(dw, dw);
    }
    dred[tid] = sacc;
    __syncthreads();
    for (int stride = 128; stride > 0; stride >>= 1) {
        if (tid < stride) dred[tid] += dred[tid + stride];
        __syncthreads();
    }
    if (tid == 0) g_partial[blockIdx.x] = dred[0];
}

// ---------------------------------------------------------------------------
// finalize (parallel, deterministic fixed-tree reductions in double).
// ---------------------------------------------------------------------------
__global__ void __launch_bounds__(256) vq_finalize(float* __restrict__ out) {
    __shared__ double dr[256];
    __shared__ double hr[256];
    __shared__ int    cr[256];
    const int tid = threadIdx.x;

    double s = 0.0;
    #pragma unroll
    for (int q = 0; q < 4; q++) s += g_partial[tid * 4 + q];
    dr[tid] = s;

    int c = 0;
    #pragma unroll
    for (int q = 0; q < 4; q++) c += g_counts[tid * 4 + q];
    cr[tid] = c;
    __syncthreads();
    for (int st = 128; st > 0; st >>= 1) {
        if (tid < st) { dr[tid] += dr[tid + st]; cr[tid] += cr[tid + st]; }
        __syncthreads();
    }
    float denom = __fadd_rn((float)cr[0], EPS_F);

    double h = 0.0;
    #pragma unroll
    for (int q = 0; q < 4; q++) {
        float p = __fdiv_rn((float)g_counts[tid * 4 + q], denom);
        h += (double)__fmul_rn(p, __logf(__fadd_rn(p, EPS_F)));
    }
    hr[tid] = h;
    __syncthreads();
    for (int st = 128; st > 0; st >>= 1) {
        if (tid < st) hr[tid] += hr[tid + st];
        __syncthreads();
    }

    if (tid == 0) {
        float L = (float)(dr[0] / (double)Z_ELEMS);
        out[Z_ELEMS + 0] = L;                                 // commitment
        out[Z_ELEMS + 1] = L;                                 // codebook
        out[Z_ELEMS + 2] = __fadd_rn(L, __fmul_rn(BETA, L));  // cluster
        out[Z_ELEMS + 3] = __expf(-(float)hr[0]);             // perplexity
    }
}

// ---------------------------------------------------------------------------
extern "C" void kernel_launch(void* const* d_in, const int* in_sizes, int n_in,
                              void* d_out, int out_size) {
    const float* z  = (const float*)d_in[0];   // [65536, 256]
    const float* cb = (const float*)d_in[1];   // [1024, 256]
    float* out = (float*)d_out;

    cudaFuncSetAttribute(vq_argmin, cudaFuncAttributeMaxDynamicSharedMemorySize,
                         SMEM_BYTES);

    vq_prep_cb_kernel<<<KCODES / 32, 256>>>(cb);
    vq_prep_z2_kernel<<<TOKENS / 32, 256>>>(z);
    vq_argmin<<<NBLK_A, 256, SMEM_BYTES>>>(z, cb, out);
    vq_finalize<<<1, 256>>>(out);
}

// round 11
// speedup vs baseline: 1.9356x; 1.9356x over previous
#include <cuda_runtime.h>
#include <cuda_bf16.h>

// Problem constants
#define TOKENS   65536          // 16*64*64
#define DDIM     256
#define KCODES   1024
#define Z_ELEMS  (TOKENS * DDIM)   // 16777216
#define BETA     0.25f
#define EPS_F    1e-5f

// Certified candidate window: |dist_bf16 - dist_f32| <= 2.3e-3 worst case
// (2 * 2^-9 rel rounding on z,e; ||z||<=19, ||e||<=16/1024). W > 2*bound.
#define W_WINDOW 0.008f
#define CAND_CAP 128

#define NBLK_MMA  (TOKENS / 64)        // 1024  (64 tokens per CTA)
#define NBLK_RR   (TOKENS / 8)         // 8192  (8 tokens per CTA)

// Phase-1 smem: z bf16 [64][264] | cb stages 2x[256][40] bf16 | z2[64] e2[1024]
#define P1_ZB_ELEMS   (64 * 264)                   // 16896 bf16
#define P1_CB_ELEMS   (256 * 40)                   // per stage
#define P1_SMEM_BYTES (P1_ZB_ELEMS * 2 + 2 * P1_CB_ELEMS * 2 + (64 + 1024) * 4) // 79104

// Output layout: [0..Z) z_q_st | [Z+0..3] scalars | [Z+4..) indices as float

// Device scratch (static: no allocations allowed)
__device__ int            g_counts[KCODES];
__device__ double         g_partial[NBLK_RR];
__device__ float          g_e2[KCODES];
__device__ float          g_z2[TOKENS];
__device__ __nv_bfloat16  g_cb_bf16[KCODES * DDIM];
__device__ __nv_bfloat16  g_z_bf16[TOKENS * DDIM];
__device__ float          g_dist[(size_t)TOKENS * KCODES];   // 268 MB

// ---------------------------------------------------------------------------
// prep codebook: exact e2 (reference order) + bf16 copy + zero histogram.
// ---------------------------------------------------------------------------
__global__ void __launch_bounds__(256) vq_prep_cb(const float* __restrict__ cb) {
    __shared__ float ct[32 * 260];
    const int tid = threadIdx.x;
    const int k0  = blockIdx.x * 32;
    if (blockIdx.x < 4) g_counts[blockIdx.x * 256 + tid] = 0;
    const float* cbb = cb + (size_t)k0 * DDIM;
    #pragma unroll
    for (int p = 0; p < 32; p++) {
        int e = tid + p * 256;            // 0..8191
        float v = cbb[e];
        ct[(e >> 8) * 260 + (e & 255)] = v;
        g_cb_bf16[(size_t)k0 * DDIM + e] = __float2bfloat16_rn(v);
    }
    __syncthreads();
    if (tid < 32) {
        const float* row = &ct[tid * 260];
        float s = 0.0f;
        #pragma unroll 8
        for (int d = 0; d < DDIM; d++)
            s = __fadd_rn(s, __fmul_rn(row[d], row[d]));
        g_e2[k0 + tid] = s;
    }
}

// ---------------------------------------------------------------------------
// prep z: exact z2 (reference order via padded transpose) + bf16 copy.
// ---------------------------------------------------------------------------
__global__ void __launch_bounds__(256) vq_prep_z(const float* __restrict__ z) {
    __shared__ float zt[32 * 257];
    const int tid  = threadIdx.x;
    const int tok0 = blockIdx.x * 32;
    const float* zb = z + (size_t)tok0 * DDIM;
    #pragma unroll
    for (int p = 0; p < 32; p++) {
        int e = tid + p * 256;
        float v = zb[e];
        zt[(e >> 8) * 257 + (e & 255)] = v;
        g_z_bf16[(size_t)tok0 * DDIM + e] = __float2bfloat16_rn(v);
    }
    __syncthreads();
    if (tid < 32) {
        const float* row = &zt[tid * 257];
        float s = 0.0f;
        #pragma unroll 8
        for (int d = 0; d < DDIM; d++)
            s = __fadd_rn(s, __fmul_rn(row[d], row[d]));
        g_z2[tok0 + tid] = s;
    }
}

// ---------------------------------------------------------------------------
// Phase 1: bf16 mma distance matrix. CTA = 64 tokens x all 1024 codes.
// 8 warps: mw = w&3 -> token rows mw*16; nh = w>>2 -> code half nh*512.
// Per warp per chunk (16 tok x 128 codes): 64 fp32 accums, m16n8k16 mma.
// ---------------------------------------------------------------------------
__global__ void __launch_bounds__(256, 2) vq_mma() {
    extern __shared__ char smem[];
    __nv_bfloat16* zbs = reinterpret_cast<__nv_bfloat16*>(smem);       // [64][264]
    __nv_bfloat16* cbs = zbs + P1_ZB_ELEMS;                            // [2][256][40]
    float* z2s = reinterpret_cast<float*>(cbs + 2 * P1_CB_ELEMS);      // [64]
    float* e2s = z2s + 64;                                             // [1024]

    const int tid  = threadIdx.x;
    const int lane = tid & 31;
    const int w    = tid >> 5;
    const int mw   = w & 3;
    const int nh   = w >> 2;
    const int tok0 = blockIdx.x * 64;
    const int gid  = lane >> 2;     // groupID
    const int tg   = lane & 3;      // thread-in-group

    // Load z bf16 tile: 2048 x 16B, rows padded to 264.
    {
        const uint4* zg = reinterpret_cast<const uint4*>(g_z_bf16 + (size_t)tok0 * DDIM);
        #pragma unroll
        for (int p = 0; p < 8; p++) {
            int idx = tid + p * 256;          // 0..2047
            int r   = idx >> 5;               // 0..63
            int c8  = idx & 31;
            *reinterpret_cast<uint4*>(zbs + r * 264 + c8 * 8) = zg[idx];
        }
    }
    if (tid < 64) z2s[tid] = g_z2[tok0 + tid];
    #pragma unroll
    for (int p = 0; p < 4; p++) e2s[tid + p * 256] = g_e2[tid + p * 256];

    // stage SI (0..31): chunk = SI>>3, d-stage = SI&7 (32 d per stage)
    #define SL(SI, BUF)                                                          \
    do {                                                                         \
        int c_  = (SI) >> 3;                                                     \
        int st_ = (SI) & 7;                                                      \
        _Pragma("unroll")                                                        \
        for (int q = 0; q < 4; q++) {                                            \
            int idx_ = tid + q * 256;          /* 0..1023 */                     \
            int r_   = idx_ >> 2;              /* 0..255  */                     \
            int sg_  = idx_ & 3;                                                 \
            int g_   = c_ * 128 + (r_ & 127) + (r_ >> 7) * 512;                  \
            const __nv_bfloat16* src_ =                                          \
                g_cb_bf16 + (size_t)g_ * DDIM + st_ * 32 + sg_ * 8;              \
            unsigned dst_ = (unsigned)__cvta_generic_to_shared(                  \
                cbs + (BUF) * P1_CB_ELEMS + r_ * 40 + sg_ * 8);                  \
            asm volatile("cp.async.cg.shared.global [%0], [%1], 16;\n"           \
                         :: "r"(dst_), "l"(src_));                               \
        }                                                                        \
        asm volatile("cp.async.commit_group;\n" ::: "memory");                   \
    } while (0)

    SL(0, 0);
    float acc[16][4];
    int buf = 0;

    for (int c = 0; c < 4; c++) {
        #pragma unroll
        for (int nt = 0; nt < 16; nt++)
            #pragma unroll
            for (int e = 0; e < 4; e++) acc[nt][e] = 0.0f;

        for (int st = 0; st < 8; st++) {
            int sg = c * 8 + st;
            asm volatile("cp.async.wait_group 0;\n" ::: "memory");
            __syncthreads();
            if (sg + 1 < 32) SL(sg + 1, buf ^ 1);

            const __nv_bfloat16* zb =
                zbs + (mw * 16 + gid) * 264 + st * 32 + tg * 2;
            const __nv_bfloat16* cbb =
                cbs + buf * P1_CB_ELEMS + (nh * 128 + gid) * 40 + tg * 2;

            #pragma unroll
            for (int k16 = 0; k16 < 2; k16++) {
                unsigned a0 = *reinterpret_cast<const unsigned*>(zb + k16 * 16);
                unsigned a1 = *reinterpret_cast<const unsigned*>(zb + k16 * 16 + 8 * 264);
                unsigned a2 = *reinterpret_cast<const unsigned*>(zb + k16 * 16 + 8);
                unsigned a3 = *reinterpret_cast<const unsigned*>(zb + k16 * 16 + 8 * 264 + 8);
                #pragma unroll
                for (int nt = 0; nt < 16; nt++) {
                    unsigned b0 = *reinterpret_cast<const unsigned*>(
                        cbb + nt * 320 + k16 * 16);
                    unsigned b1 = *reinterpret_cast<const unsigned*>(
                        cbb + nt * 320 + k16 * 16 + 8);
                    asm volatile(
                        "mma.sync.aligned.m16n8k16.row.col.f32.bf16.bf16.f32 "
                        "{%0,%1,%2,%3}, {%4,%5,%6,%7}, {%8,%9}, {%0,%1,%2,%3};"
                        : "+f"(acc[nt][0]), "+f"(acc[nt][1]),
                          "+f"(acc[nt][2]), "+f"(acc[nt][3])
                        : "r"(a0), "r"(a1), "r"(a2), "r"(a3), "r"(b0), "r"(b1));
                }
            }
            buf ^= 1;
        }

        // epilogue: dist = z2 + e2 - 2*ze, write float2 pairs
        int t0 = mw * 16 + gid;
        #pragma unroll
        for (int nt = 0; nt < 16; nt++) {
            int kg = nh * 512 + c * 128 + nt * 8 + tg * 2;
            float2 lo, hi;
            lo.x = z2s[t0] + e2s[kg]     - 2.0f * acc[nt][0];
            lo.y = z2s[t0] + e2s[kg + 1] - 2.0f * acc[nt][1];
            hi.x = z2s[t0 + 8] + e2s[kg]     - 2.0f * acc[nt][2];
            hi.y = z2s[t0 + 8] + e2s[kg + 1] - 2.0f * acc[nt][3];
            *reinterpret_cast<float2*>(
                &g_dist[(size_t)(tok0 + t0) * KCODES + kg]) = lo;
            *reinterpret_cast<float2*>(
                &g_dist[(size_t)(tok0 + t0 + 8) * KCODES + kg]) = hi;
        }
    }
    #undef SL
}

// ---------------------------------------------------------------------------
// exact dist, bit-identical to the R2-R10 mainloop rounding:
// two fp32 FMA chains over even/odd d ascending, lo+hi, (z2+e2)-2*ze.
// ---------------------------------------------------------------------------
__device__ __forceinline__ float exact_dist(const float* __restrict__ zr,
                                            const float* __restrict__ er,
                                            float z2t, float e2k) {
    float slo = 0.0f, shi = 0.0f;
    #pragma unroll 8
    for (int dd = 0; dd < DDIM / 2; dd++) {
        float2 zp = *reinterpret_cast<const float2*>(zr + 2 * dd);
        float2 ep = *reinterpret_cast<const float2*>(er + 2 * dd);
        slo = __fmaf_rn(zp.x, ep.x, slo);
        shi = __fmaf_rn(zp.y, ep.y, shi);
    }
    float ze = __fadd_rn(slo, shi);
    return __fsub_rn(__fadd_rn(z2t, e2k), __fmul_rn(2.0f, ze));
}

// ---------------------------------------------------------------------------
// Phase 2: per token (1 warp): min over approx dists, candidate select,
// exact re-rank, then fused gather + z_q_st + loss + histogram.
// ---------------------------------------------------------------------------
__global__ void __launch_bounds__(256)
vq_rerank(const float* __restrict__ z, const float* __restrict__ cb,
          float* __restrict__ out) {
    __shared__ float  zsr[8 * DDIM];          // 8 token rows fp32
    __shared__ int    cand[8][CAND_CAP];
    __shared__ int    ccnt[8];
    __shared__ int    sfin[8];
    __shared__ double dred[256];

    const int tid  = threadIdx.x;
    const int lane = tid & 31;
    const int w    = tid >> 5;
    const int tok0 = blockIdx.x * 8;
    const int t    = tok0 + w;

    // stage z rows (512 float4)
    {
        const float4* zg = reinterpret_cast<const float4*>(z) + (size_t)tok0 * (DDIM / 4);
        #pragma unroll
        for (int p = 0; p < 2; p++) {
            int idx = tid + p * 256;
            reinterpret_cast<float4*>(zsr)[idx] = zg[idx];
        }
    }
    if (tid < 8) ccnt[tid] = 0;
    __syncthreads();

    // load this token's dist row; warp min
    const float4* dv = reinterpret_cast<const float4*>(g_dist) + (size_t)t * (KCODES / 4);
    float4 d[8];
    float m = 3.4e38f;
    #pragma unroll
    for (int p = 0; p < 8; p++) {
        d[p] = dv[p * 32 + lane];
        m = fminf(m, fminf(fminf(d[p].x, d[p].y), fminf(d[p].z, d[p].w)));
    }
    #pragma unroll
    for (int off = 16; off > 0; off >>= 1)
        m = fminf(m, __shfl_xor_sync(0xFFFFFFFFu, m, off));
    const float thr = m + W_WINDOW;

    // candidate selection
    #pragma unroll
    for (int p = 0; p < 8; p++) {
        int kb = (p * 32 + lane) * 4;
        float v[4] = {d[p].x, d[p].y, d[p].z, d[p].w};
        #pragma unroll
        for (int e = 0; e < 4; e++) {
            if (v[e] <= thr) {
                int pos = atomicAdd(&ccnt[w], 1);
                if (pos < CAND_CAP) cand[w][pos] = kb + e;
            }
        }
    }
    __syncwarp();
    const int cnt = ccnt[w];

    // exact re-rank (lex-min on (dist, k))
    float bd = 3.4e38f;
    int   bk = 0;
    const float* zr  = zsr + w * DDIM;
    const float  z2t = g_z2[t];
    if (cnt <= CAND_CAP) {
        for (int cc = lane; cc < cnt; cc += 32) {
            int k = cand[w][cc];
            float dist = exact_dist(zr, cb + (size_t)k * DDIM, z2t, g_e2[k]);
            if (dist < bd || (dist == bd && k < bk)) { bd = dist; bk = k; }
        }
    } else {
        // overflow fallback: full exact scan (probability ~0)
        for (int k = lane; k < KCODES; k += 32) {
            float dist = exact_dist(zr, cb + (size_t)k * DDIM, z2t, g_e2[k]);
            if (dist < bd || (dist == bd && k < bk)) { bd = dist; bk = k; }
        }
    }
    #pragma unroll
    for (int off = 16; off > 0; off >>= 1) {
        float od = __shfl_down_sync(0xFFFFFFFFu, bd, off);
        int   ok = __shfl_down_sync(0xFFFFFFFFu, bk, off);
        if (od < bd || (od == bd && ok < bk)) { bd = od; bk = ok; }
    }
    if (lane == 0) {
        sfin[w] = bk;
        out[Z_ELEMS + 4 + t] = (float)bk;
        atomicAdd(&g_counts[bk], 1);
    }
    __syncthreads();

    // fused gather + z_q_st + loss partial
    double sacc = 0.0;
    const float4* cb4 = reinterpret_cast<const float4*>(cb);
    float4*       o4  = reinterpret_cast<float4*>(out);
    #pragma unroll
    for (int p = 0; p < 2; p++) {
        int e4 = tid + p * 256;           // 0..511
        int tl = e4 >> 6;
        int d4 = e4 & 63;
        int idx = sfin[tl];
        float4 zq = cb4[(size_t)idx * (DDIM / 4) + d4];
        float4 zz = reinterpret_cast<const float4*>(zsr)[e4];
        float4 o;
        o.x = __fadd_rn(zz.x, __fsub_rn(zq.x, zz.x));
        o.y = __fadd_rn(zz.y, __fsub_rn(zq.y, zz.y));
        o.z = __fadd_rn(zz.z, __fsub_rn(zq.z, zz.z));
        o.w = __fadd_rn(zz.w, __fsub_rn(zq.w, zz.w));
        o4[(size_t)tok0 * (DDIM / 4) + e4] = o;
        float dx = __fsub_rn(zz.x, zq.x);
        float dy = __fsub_rn(zz.y, zq.y);
        float dz = __fsub_rn(zz.z, zq.z);
        float dw = __fsub_rn(zz.w, zq.w);
        sacc += (double)__fmul_rn(dx, dx);
        sacc += (double)__fmul_rn(dy, dy);
        sacc += (double)__fmul_rn(dz, dz);
        sacc += (double)__fmul_rn(dw, dw);
    }
    dred[tid] = sacc;
    __syncthreads();
    for (int stride = 128; stride > 0; stride >>= 1) {
        if (tid < stride) dred[tid] += dred[tid + stride];
        __syncthreads();
    }
    if (tid == 0) g_partial[blockIdx.x] = dred[0];
}

// ---------------------------------------------------------------------------
// finalize (parallel, deterministic fixed-tree reductions in double).
// ---------------------------------------------------------------------------
__global__ void __launch_bounds__(256) vq_finalize(float* __restrict__ out) {
    __shared__ double dr[256];
    __shared__ double hr[256];
    __shared__ int    cr[256];
    const int tid = threadIdx.x;

    double s = 0.0;
    for (int q = 0; q < NBLK_RR / 256; q++) s += g_partial[tid * (NBLK_RR / 256) + q];
    dr[tid] = s;

    int c = 0;
    #pragma unroll
    for (int q = 0; q < 4; q++) c += g_counts[tid * 4 + q];
    cr[tid] = c;
    __syncthreads();
    for (int st = 128; st > 0; st >>= 1) {
        if (tid < st) { dr[tid] += dr[tid + st]; cr[tid] += cr[tid + st]; }
        __syncthreads();
    }
    float denom = __fadd_rn((float)cr[0], EPS_F);

    double h = 0.0;
    #pragma unroll
    for (int q = 0; q < 4; q++) {
        float p = __fdiv_rn((float)g_counts[tid * 4 + q], denom);
        h += (double)__fmul_rn(p, __logf(__fadd_rn(p, EPS_F)));
    }
    hr[tid] = h;
    __syncthreads();
    for (int st = 128; st > 0; st >>= 1) {
        if (tid < st) hr[tid] += hr[tid + st];
        __syncthreads();
    }

    if (tid == 0) {
        float L = (float)(dr[0] / (double)Z_ELEMS);
        out[Z_ELEMS + 0] = L;                                 // commitment
        out[Z_ELEMS + 1] = L;                                 // codebook
        out[Z_ELEMS + 2] = __fadd_rn(L, __fmul_rn(BETA, L));  // cluster
        out[Z_ELEMS + 3] = __expf(-(float)hr[0]);             // perplexity
    }
}

// ---------------------------------------------------------------------------
extern "C" void kernel_launch(void* const* d_in, const int* in_sizes, int n_in,
                              void* d_out, int out_size) {
    const float* z  = (const float*)d_in[0];   // [65536, 256]
    const float* cb = (const float*)d_in[1];   // [1024, 256]
    float* out = (float*)d_out;

    cudaFuncSetAttribute(vq_mma, cudaFuncAttributeMaxDynamicSharedMemorySize,
                         P1_SMEM_BYTES);

    vq_prep_cb<<<KCODES / 32, 256>>>(cb);
    vq_prep_z<<<TOKENS / 32, 256>>>(z);
    vq_mma<<<NBLK_MMA, 256, P1_SMEM_BYTES>>>();
    vq_rerank<<<NBLK_RR, 256>>>(z, cb, out);
    vq_finalize<<<1, 256>>>(out);
}

// round 12
// speedup vs baseline: 2.3362x; 1.2070x over previous
#include <cuda_runtime.h>
#include <cuda_bf16.h>
#include <cuda_fp16.h>

// Problem constants
#define TOKENS   65536          // 16*64*64
#define DDIM     256
#define KCODES   1024
#define Z_ELEMS  (TOKENS * DDIM)   // 16777216
#define BETA     0.25f
#define EPS_F    1e-5f

// Certified window on s = e2 - 2*ze (fp16-stored):
//   E = mma bf16 error (<=2.4e-3) + fp16 quant (<=3e-4);  need m + 2E; W=0.01.
#define W_WINDOW 0.01f
#define CAND_CAP 128

#define NBLK_MMA  (TOKENS / 64)        // 1024  (64 tokens per CTA)
#define NBLK_RR   (TOKENS / 8)         // 8192  (8 tokens per CTA)

// Phase-1 smem: z bf16 [64][264] | cb stages 2x[256][40] bf16 | e2[1024]
#define P1_ZB_ELEMS   (64 * 264)                   // 16896 bf16
#define P1_CB_ELEMS   (256 * 40)                   // per stage
#define P1_SMEM_BYTES (P1_ZB_ELEMS * 2 + 2 * P1_CB_ELEMS * 2 + 1024 * 4) // 78848

// Output layout: [0..Z) z_q_st | [Z+0..3] scalars | [Z+4..) indices as float

// Device scratch (static: no allocations allowed)
__device__ int            g_counts[KCODES];
__device__ double         g_partial[NBLK_RR];
__device__ float          g_e2[KCODES];
__device__ float          g_z2[TOKENS];
__device__ __nv_bfloat16  g_cb_bf16[KCODES * DDIM];
__device__ __nv_bfloat16  g_z_bf16[TOKENS * DDIM];
__device__ __half         g_s[(size_t)TOKENS * KCODES];   // 134 MB

// ---------------------------------------------------------------------------
// prep codebook: exact e2 (reference order) + bf16 copy + zero histogram.
// ---------------------------------------------------------------------------
__global__ void __launch_bounds__(256) vq_prep_cb(const float* __restrict__ cb) {
    __shared__ float ct[32 * 260];
    const int tid = threadIdx.x;
    const int k0  = blockIdx.x * 32;
    if (blockIdx.x < 4) g_counts[blockIdx.x * 256 + tid] = 0;
    const float* cbb = cb + (size_t)k0 * DDIM;
    #pragma unroll
    for (int p = 0; p < 32; p++) {
        int e = tid + p * 256;            // 0..8191
        float v = cbb[e];
        ct[(e >> 8) * 260 + (e & 255)] = v;
        g_cb_bf16[(size_t)k0 * DDIM + e] = __float2bfloat16_rn(v);
    }
    __syncthreads();
    if (tid < 32) {
        const float* row = &ct[tid * 260];
        float s = 0.0f;
        #pragma unroll 8
        for (int d = 0; d < DDIM; d++)
            s = __fadd_rn(s, __fmul_rn(row[d], row[d]));
        g_e2[k0 + tid] = s;
    }
}

// ---------------------------------------------------------------------------
// prep z: exact z2 (reference order via padded transpose) + bf16 copy.
// ---------------------------------------------------------------------------
__global__ void __launch_bounds__(256) vq_prep_z(const float* __restrict__ z) {
    __shared__ float zt[32 * 257];
    const int tid  = threadIdx.x;
    const int tok0 = blockIdx.x * 32;
    const float* zb = z + (size_t)tok0 * DDIM;
    #pragma unroll
    for (int p = 0; p < 32; p++) {
        int e = tid + p * 256;
        float v = zb[e];
        zt[(e >> 8) * 257 + (e & 255)] = v;
        g_z_bf16[(size_t)tok0 * DDIM + e] = __float2bfloat16_rn(v);
    }
    __syncthreads();
    if (tid < 32) {
        const float* row = &zt[tid * 257];
        float s = 0.0f;
        #pragma unroll 8
        for (int d = 0; d < DDIM; d++)
            s = __fadd_rn(s, __fmul_rn(row[d], row[d]));
        g_z2[tok0 + tid] = s;
    }
}

// ---------------------------------------------------------------------------
// Phase 1: bf16 mma, s = e2 - 2*ze stored fp16. CTA = 64 tokens x 1024 codes.
// 8 warps: mw = w&3 -> token rows mw*16; nh = w>>2 -> code half nh*512.
// ---------------------------------------------------------------------------
__global__ void __launch_bounds__(256, 2) vq_mma() {
    extern __shared__ char smem[];
    __nv_bfloat16* zbs = reinterpret_cast<__nv_bfloat16*>(smem);       // [64][264]
    __nv_bfloat16* cbs = zbs + P1_ZB_ELEMS;                            // [2][256][40]
    float* e2s = reinterpret_cast<float*>(cbs + 2 * P1_CB_ELEMS);      // [1024]

    const int tid  = threadIdx.x;
    const int lane = tid & 31;
    const int w    = tid >> 5;
    const int mw   = w & 3;
    const int nh   = w >> 2;
    const int tok0 = blockIdx.x * 64;
    const int gid  = lane >> 2;     // groupID
    const int tg   = lane & 3;      // thread-in-group

    // Load z bf16 tile: 2048 x 16B, rows padded to 264.
    {
        const uint4* zg = reinterpret_cast<const uint4*>(g_z_bf16 + (size_t)tok0 * DDIM);
        #pragma unroll
        for (int p = 0; p < 8; p++) {
            int idx = tid + p * 256;          // 0..2047
            int r   = idx >> 5;               // 0..63
            int c8  = idx & 31;
            *reinterpret_cast<uint4*>(zbs + r * 264 + c8 * 8) = zg[idx];
        }
    }
    #pragma unroll
    for (int p = 0; p < 4; p++) e2s[tid + p * 256] = g_e2[tid + p * 256];

    // stage SI (0..31): chunk = SI>>3, d-stage = SI&7 (32 d per stage)
    #define SL(SI, BUF)                                                          \
    do {                                                                         \
        int c_  = (SI) >> 3;                                                     \
        int st_ = (SI) & 7;                                                      \
        _Pragma("unroll")                                                        \
        for (int q = 0; q < 4; q++) {                                            \
            int idx_ = tid + q * 256;          /* 0..1023 */                     \
            int r_   = idx_ >> 2;              /* 0..255  */                     \
            int sg_  = idx_ & 3;                                                 \
            int g_   = c_ * 128 + (r_ & 127) + (r_ >> 7) * 512;                  \
            const __nv_bfloat16* src_ =                                          \
                g_cb_bf16 + (size_t)g_ * DDIM + st_ * 32 + sg_ * 8;              \
            unsigned dst_ = (unsigned)__cvta_generic_to_shared(                  \
                cbs + (BUF) * P1_CB_ELEMS + r_ * 40 + sg_ * 8);                  \
            asm volatile("cp.async.cg.shared.global [%0], [%1], 16;\n"           \
                         :: "r"(dst_), "l"(src_));                               \
        }                                                                        \
        asm volatile("cp.async.commit_group;\n" ::: "memory");                   \
    } while (0)

    SL(0, 0);
    float acc[16][4];
    int buf = 0;

    for (int c = 0; c < 4; c++) {
        #pragma unroll
        for (int nt = 0; nt < 16; nt++)
            #pragma unroll
            for (int e = 0; e < 4; e++) acc[nt][e] = 0.0f;

        for (int st = 0; st < 8; st++) {
            int sg = c * 8 + st;
            asm volatile("cp.async.wait_group 0;\n" ::: "memory");
            __syncthreads();
            if (sg + 1 < 32) SL(sg + 1, buf ^ 1);

            const __nv_bfloat16* zb =
                zbs + (mw * 16 + gid) * 264 + st * 32 + tg * 2;
            const __nv_bfloat16* cbb =
                cbs + buf * P1_CB_ELEMS + (nh * 128 + gid) * 40 + tg * 2;

            #pragma unroll
            for (int k16 = 0; k16 < 2; k16++) {
                unsigned a0 = *reinterpret_cast<const unsigned*>(zb + k16 * 16);
                unsigned a1 = *reinterpret_cast<const unsigned*>(zb + k16 * 16 + 8 * 264);
                unsigned a2 = *reinterpret_cast<const unsigned*>(zb + k16 * 16 + 8);
                unsigned a3 = *reinterpret_cast<const unsigned*>(zb + k16 * 16 + 8 * 264 + 8);
                #pragma unroll
                for (int nt = 0; nt < 16; nt++) {
                    unsigned b0 = *reinterpret_cast<const unsigned*>(
                        cbb + nt * 320 + k16 * 16);
                    unsigned b1 = *reinterpret_cast<const unsigned*>(
                        cbb + nt * 320 + k16 * 16 + 8);
                    asm volatile(
                        "mma.sync.aligned.m16n8k16.row.col.f32.bf16.bf16.f32 "
                        "{%0,%1,%2,%3}, {%4,%5,%6,%7}, {%8,%9}, {%0,%1,%2,%3};"
                        : "+f"(acc[nt][0]), "+f"(acc[nt][1]),
                          "+f"(acc[nt][2]), "+f"(acc[nt][3])
                        : "r"(a0), "r"(a1), "r"(a2), "r"(a3), "r"(b0), "r"(b1));
                }
            }
            buf ^= 1;
        }

        // epilogue: s = e2 - 2*ze, fp16 pairs
        int t0 = mw * 16 + gid;
        #pragma unroll
        for (int nt = 0; nt < 16; nt++) {
            int kg = nh * 512 + c * 128 + nt * 8 + tg * 2;
            float e20 = e2s[kg], e21 = e2s[kg + 1];
            __half2 lo = __floats2half2_rn(e20 - 2.0f * acc[nt][0],
                                           e21 - 2.0f * acc[nt][1]);
            __half2 hi = __floats2half2_rn(e20 - 2.0f * acc[nt][2],
                                           e21 - 2.0f * acc[nt][3]);
            *reinterpret_cast<__half2*>(
                &g_s[(size_t)(tok0 + t0) * KCODES + kg]) = lo;
            *reinterpret_cast<__half2*>(
                &g_s[(size_t)(tok0 + t0 + 8) * KCODES + kg]) = hi;
        }
    }
    #undef SL
}

// ---------------------------------------------------------------------------
// Phase 2: per token (1 warp): min over fp16 s row, candidate select,
// warp-cooperative exact re-rank, fused gather + z_q_st + loss + histogram.
// ---------------------------------------------------------------------------
__global__ void __launch_bounds__(256)
vq_rerank(const float* __restrict__ z, const float* __restrict__ cb,
          float* __restrict__ out) {
    __shared__ float  zsr[8 * DDIM];          // 8 token rows fp32
    __shared__ int    cand[8][CAND_CAP];
    __shared__ int    ccnt[8];
    __shared__ int    sfin[8];
    __shared__ double dred[256];

    const int tid  = threadIdx.x;
    const int lane = tid & 31;
    const int w    = tid >> 5;
    const int tok0 = blockIdx.x * 8;
    const int t    = tok0 + w;

    // stage z rows (512 float4)
    {
        const float4* zg = reinterpret_cast<const float4*>(z) + (size_t)tok0 * (DDIM / 4);
        #pragma unroll
        for (int p = 0; p < 2; p++) {
            int idx = tid + p * 256;
            reinterpret_cast<float4*>(zsr)[idx] = zg[idx];
        }
    }
    if (tid < 8) ccnt[tid] = 0;
    __syncthreads();

    // load this token's s row (fp16): 128 uint4 = 1024 halves; 4 per lane
    const uint4* sv = reinterpret_cast<const uint4*>(g_s + (size_t)t * KCODES);
    uint4 raw[4];
    float m = 3.4e38f;
    #pragma unroll
    for (int p = 0; p < 4; p++) {
        raw[p] = sv[p * 32 + lane];
        const __half2* h2 = reinterpret_cast<const __half2*>(&raw[p]);
        #pragma unroll
        for (int q = 0; q < 4; q++) {
            float2 f2 = __half22float2(h2[q]);
            m = fminf(m, fminf(f2.x, f2.y));
        }
    }
    #pragma unroll
    for (int off = 16; off > 0; off >>= 1)
        m = fminf(m, __shfl_xor_sync(0xFFFFFFFFu, m, off));
    const float thr = m + W_WINDOW;

    // candidate selection
    #pragma unroll
    for (int p = 0; p < 4; p++) {
        const __half2* h2 = reinterpret_cast<const __half2*>(&raw[p]);
        int kb = (p * 32 + lane) * 8;
        #pragma unroll
        for (int q = 0; q < 4; q++) {
            float2 f2 = __half22float2(h2[q]);
            if (f2.x <= thr) {
                int pos = atomicAdd(&ccnt[w], 1);
                if (pos < CAND_CAP) cand[w][pos] = kb + q * 2;
            }
            if (f2.y <= thr) {
                int pos = atomicAdd(&ccnt[w], 1);
                if (pos < CAND_CAP) cand[w][pos] = kb + q * 2 + 1;
            }
        }
    }
    __syncwarp();
    const int cnt = ccnt[w];

    // warp-cooperative exact re-rank: lane covers d = lane*8..lane*8+7,
    // fixed shfl_xor butterfly; all lanes end with identical (bd, bk).
    float bd = 3.4e38f;
    int   bk = 0;
    const float* zr  = zsr + w * DDIM;
    const float  z2t = g_z2[t];
    const float4* zr4 = reinterpret_cast<const float4*>(zr) + lane * 2;
    float4 zv0 = zr4[0], zv1 = zr4[1];

    if (cnt <= CAND_CAP) {
        for (int cc = 0; cc < cnt; cc++) {
            int k = cand[w][cc];
            const float4* er = reinterpret_cast<const float4*>(
                cb + (size_t)k * DDIM) + lane * 2;
            float4 e0 = er[0], e1 = er[1];
            float s = 0.0f;
            s = __fmaf_rn(zv0.x, e0.x, s);
            s = __fmaf_rn(zv0.y, e0.y, s);
            s = __fmaf_rn(zv0.z, e0.z, s);
            s = __fmaf_rn(zv0.w, e0.w, s);
            s = __fmaf_rn(zv1.x, e1.x, s);
            s = __fmaf_rn(zv1.y, e1.y, s);
            s = __fmaf_rn(zv1.z, e1.z, s);
            s = __fmaf_rn(zv1.w, e1.w, s);
            #pragma unroll
            for (int off = 16; off > 0; off >>= 1)
                s = __fadd_rn(s, __shfl_xor_sync(0xFFFFFFFFu, s, off));
            float dist = __fsub_rn(__fadd_rn(z2t, g_e2[k]),
                                   __fmul_rn(2.0f, s));
            if (dist < bd || (dist == bd && k < bk)) { bd = dist; bk = k; }
        }
    } else {
        // overflow fallback: full exact scan (probability ~0)
        for (int k = 0; k < KCODES; k++) {
            const float4* er = reinterpret_cast<const float4*>(
                cb + (size_t)k * DDIM) + lane * 2;
            float4 e0 = er[0], e1 = er[1];
            float s = 0.0f;
            s = __fmaf_rn(zv0.x, e0.x, s);
            s = __fmaf_rn(zv0.y, e0.y, s);
            s = __fmaf_rn(zv0.z, e0.z, s);
            s = __fmaf_rn(zv0.w, e0.w, s);
            s = __fmaf_rn(zv1.x, e1.x, s);
            s = __fmaf_rn(zv1.y, e1.y, s);
            s = __fmaf_rn(zv1.z, e1.z, s);
            s = __fmaf_rn(zv1.w, e1.w, s);
            #pragma unroll
            for (int off = 16; off > 0; off >>= 1)
                s = __fadd_rn(s, __shfl_xor_sync(0xFFFFFFFFu, s, off));
            float dist = __fsub_rn(__fadd_rn(z2t, g_e2[k]),
                                   __fmul_rn(2.0f, s));
            if (dist < bd || (dist == bd && k < bk)) { bd = dist; bk = k; }
        }
    }
    if (lane == 0) {
        sfin[w] = bk;
        out[Z_ELEMS + 4 + t] = (float)bk;
        atomicAdd(&g_counts[bk], 1);
    }
    __syncthreads();

    // fused gather + z_q_st + loss partial
    double sacc = 0.0;
    const float4* cb4 = reinterpret_cast<const float4*>(cb);
    float4*       o4  = reinterpret_cast<float4*>(out);
    #pragma unroll
    for (int p = 0; p < 2; p++) {
        int e4 = tid + p * 256;           // 0..511
        int tl = e4 >> 6;
        int d4 = e4 & 63;
        int idx = sfin[tl];
        float4 zq = cb4[(size_t)idx * (DDIM / 4) + d4];
        float4 zz = reinterpret_cast<const float4*>(zsr)[e4];
        float4 o;
        o.x = __fadd_rn(zz.x, __fsub_rn(zq.x, zz.x));
        o.y = __fadd_rn(zz.y, __fsub_rn(zq.y, zz.y));
        o.z = __fadd_rn(zz.z, __fsub_rn(zq.z, zz.z));
        o.w = __fadd_rn(zz.w, __fsub_rn(zq.w, zz.w));
        o4[(size_t)tok0 * (DDIM / 4) + e4] = o;
        float dx = __fsub_rn(zz.x, zq.x);
        float dy = __fsub_rn(zz.y, zq.y);
        float dz = __fsub_rn(zz.z, zq.z);
        float dw = __fsub_rn(zz.w, zq.w);
        sacc += (double)__fmul_rn(dx, dx);
        sacc += (double)__fmul_rn(dy, dy);
        sacc += (double)__fmul_rn(dz, dz);
        sacc += (double)__fmul_rn(dw, dw);
    }
    dred[tid] = sacc;
    __syncthreads();
    for (int stride = 128; stride > 0; stride >>= 1) {
        if (tid < stride) dred[tid] += dred[tid + stride];
        __syncthreads();
    }
    if (tid == 0) g_partial[blockIdx.x] = dred[0];
}

// ---------------------------------------------------------------------------
// finalize (parallel, deterministic fixed-tree reductions in double).
// ---------------------------------------------------------------------------
__global__ void __launch_bounds__(256) vq_finalize(float* __restrict__ out) {
    __shared__ double dr[256];
    __shared__ double hr[256];
    __shared__ int    cr[256];
    const int tid = threadIdx.x;

    double s = 0.0;
    for (int q = 0; q < NBLK_RR / 256; q++) s += g_partial[tid * (NBLK_RR / 256) + q];
    dr[tid] = s;

    int c = 0;
    #pragma unroll
    for (int q = 0; q < 4; q++) c += g_counts[tid * 4 + q];
    cr[tid] = c;
    __syncthreads();
    for (int st = 128; st > 0; st >>= 1) {
        if (tid < st) { dr[tid] += dr[tid + st]; cr[tid] += cr[tid + st]; }
        __syncthreads();
    }
    float denom = __fadd_rn((float)cr[0], EPS_F);

    double h = 0.0;
    #pragma unroll
    for (int q = 0; q < 4; q++) {
        float p = __fdiv_rn((float)g_counts[tid * 4 + q], denom);
        h += (double)__fmul_rn(p, __logf(__fadd_rn(p, EPS_F)));
    }
    hr[tid] = h;
    __syncthreads();
    for (int st = 128; st > 0; st >>= 1) {
        if (tid < st) hr[tid] += hr[tid + st];
        __syncthreads();
    }

    if (tid == 0) {
        float L = (float)(dr[0] / (double)Z_ELEMS);
        out[Z_ELEMS + 0] = L;                                 // commitment
        out[Z_ELEMS + 1] = L;                                 // codebook
        out[Z_ELEMS + 2] = __fadd_rn(L, __fmul_rn(BETA, L));  // cluster
        out[Z_ELEMS + 3] = __expf(-(float)hr[0]);             // perplexity
    }
}

// ---------------------------------------------------------------------------
extern "C" void kernel_launch(void* const* d_in, const int* in_sizes, int n_in,
                              void* d_out, int out_size) {
    const float* z  = (const float*)d_in[0];   // [65536, 256]
    const float* cb = (const float*)d_in[1];   // [1024, 256]
    float* out = (float*)d_out;

    cudaFuncSetAttribute(vq_mma, cudaFuncAttributeMaxDynamicSharedMemorySize,
                         P1_SMEM_BYTES);

    vq_prep_cb<<<KCODES / 32, 256>>>(cb);
    vq_prep_z<<<TOKENS / 32, 256>>>(z);
    vq_mma<<<NBLK_MMA, 256, P1_SMEM_BYTES>>>();
    vq_rerank<<<NBLK_RR, 256>>>(z, cb, out);
    vq_finalize<<<1, 256>>>(out);
}